// round 4
// baseline (speedup 1.0000x reference)
#include <cuda_runtime.h>
#include <cuda_bf16.h>

// Problem constants (fixed by the reference setup_inputs)
#define BATCH        16
#define HW           512
#define MCOMP        200000
#define NTHR         256
#define CHUNK_PAIRS  (2 * NTHR)                 // 512 pairs per chunk
#define MAXPAIRS     (MCOMP / 2)                // 100000
#define MAXCHUNKB    ((MAXPAIRS + CHUNK_PAIRS - 1) / CHUNK_PAIRS)   // 196
#define MAXCHUNKS    (BATCH * MAXCHUNKB)        // 3136

#define EPS_F   1e-10f
#define THR_F   1.1f            // 1.0 + DELTA

// Scratch: per-chunk partial sums (sum_w, sum_w*mismatch) + completion counter
__device__ float2 g_part[MAXCHUNKS];
__device__ unsigned int g_count;   // zero-init; reset by last block each run

__device__ __forceinline__ void whdr_eval(float x1f, float y1f, float x2f, float y2f,
                                          float darkerf, float w,
                                          const float* __restrict__ img,
                                          float& ws, float& wm)
{
    const int x1 = (int)x1f, y1 = (int)y1f;
    const int x2 = (int)x2f, y2 = (int)y2f;
    const int darker = (int)darkerf;

    const float r1 = __ldg(img + y1 * HW + x1);
    const float r2 = __ldg(img + y2 * HW + x2);

    // alg = 1 if r2/(r1+eps) > thr ; 2 if r1/(r2+eps) > thr ; else 0
    int alg = 0;
    if (r2 > THR_F * (r1 + EPS_F))      alg = 1;
    else if (r1 > THR_F * (r2 + EPS_F)) alg = 2;

    ws += w;
    if (alg != darker) wm += w;
}

__global__ __launch_bounds__(NTHR)
void whdr_kernel(const float* __restrict__ v_input,
                 const float* __restrict__ comparisons,
                 const int*   __restrict__ numComparisons,
                 float* __restrict__ out)
{
    __shared__ int s_n[BATCH];
    __shared__ int s_coff[BATCH + 1];   // chunk-offset prefix per batch

    const int tid  = threadIdx.x;
    const int lane = tid & 31;
    const int warp = tid >> 5;

    if (tid < BATCH) s_n[tid] = numComparisons[tid];
    __syncthreads();
    if (tid == 0) {
        int acc = 0;
        s_coff[0] = 0;
        #pragma unroll
        for (int i = 0; i < BATCH; i++) {
            const int pr = s_n[i] >> 1;
            acc += (pr + CHUNK_PAIRS - 1) / CHUNK_PAIRS;
            s_coff[i + 1] = acc;
        }
    }
    __syncthreads();

    const int c = blockIdx.x;
    const int total_chunks = s_coff[BATCH];

    float ws = 0.0f, wm = 0.0f;

    if (c < total_chunks) {
        // find batch of this chunk
        int b = 0;
        #pragma unroll
        for (int i = 1; i < BATCH; i++) b += (c >= s_coff[i]);

        const int nb = s_n[b];
        const int Pb = nb >> 1;
        const int sp = (c - s_coff[b]) * CHUNK_PAIRS;

        const float* __restrict__ img = v_input + (size_t)b * HW * HW;
        const float* __restrict__ cb  = comparisons + (size_t)b * MCOMP * 6;
        const float4* __restrict__ c4 = (const float4*)cb;

        const int p0 = sp + tid;
        const int p1 = p0 + NTHR;
        const bool v0 = p0 < Pb;
        const bool v1 = p1 < Pb;
        const int p0c = v0 ? p0 : 0;     // clamp so loads are always safe
        const int p1c = v1 ? p1 : 0;

        // Issue all 6 streaming 16B loads branchlessly (MLP)
        const float4 a0 = __ldcs(c4 + (size_t)p0c * 3 + 0);
        const float4 a1 = __ldcs(c4 + (size_t)p0c * 3 + 1);
        const float4 a2 = __ldcs(c4 + (size_t)p0c * 3 + 2);
        const float4 q0 = __ldcs(c4 + (size_t)p1c * 3 + 0);
        const float4 q1 = __ldcs(c4 + (size_t)p1c * 3 + 1);
        const float4 q2 = __ldcs(c4 + (size_t)p1c * 3 + 2);

        const float w0 = v0 ? 1.0f : 0.0f;
        const float w1 = v1 ? 1.0f : 0.0f;

        // pair 0: records (2*p0, 2*p0+1)
        whdr_eval(a0.x, a0.y, a0.z, a0.w, a1.x, a1.y * w0, img, ws, wm);
        whdr_eval(a1.z, a1.w, a2.x, a2.y, a2.z, a2.w * w0, img, ws, wm);
        // pair 1: records (2*p1, 2*p1+1)
        whdr_eval(q0.x, q0.y, q0.z, q0.w, q1.x, q1.y * w1, img, ws, wm);
        whdr_eval(q1.z, q1.w, q2.x, q2.y, q2.z, q2.w * w1, img, ws, wm);

        // odd leftover record for this batch, once (first chunk, thread 0)
        if ((nb & 1) && tid == 0 && c == s_coff[b]) {
            const int m = nb - 1;
            const float2* c2 = (const float2*)cb;
            const float2 e0 = __ldcs(c2 + (size_t)m * 3 + 0);
            const float2 e1 = __ldcs(c2 + (size_t)m * 3 + 1);
            const float2 e2 = __ldcs(c2 + (size_t)m * 3 + 2);
            whdr_eval(e0.x, e0.y, e1.x, e1.y, e2.x, e2.y, img, ws, wm);
        }
    }

    // block reduction (8 warps)
    __shared__ float s_ws[NTHR / 32];
    __shared__ float s_wm[NTHR / 32];
    #pragma unroll
    for (int o = 16; o > 0; o >>= 1) {
        ws += __shfl_down_sync(0xFFFFFFFFu, ws, o);
        wm += __shfl_down_sync(0xFFFFFFFFu, wm, o);
    }
    if (lane == 0) { s_ws[warp] = ws; s_wm[warp] = wm; }
    __syncthreads();

    __shared__ bool s_last;
    if (warp == 0) {
        ws = (lane < NTHR / 32) ? s_ws[lane] : 0.0f;
        wm = (lane < NTHR / 32) ? s_wm[lane] : 0.0f;
        #pragma unroll
        for (int o = 4; o > 0; o >>= 1) {
            ws += __shfl_down_sync(0xFFFFFFFFu, ws, o);
            wm += __shfl_down_sync(0xFFFFFFFFu, wm, o);
        }
        if (lane == 0) {
            g_part[c] = make_float2(ws, wm);
            __threadfence();
            unsigned int prev = atomicAdd(&g_count, 1u);
            s_last = (prev == (unsigned int)(gridDim.x - 1));
        }
    }
    __syncthreads();

    // Last block performs the deterministic final reduction
    if (s_last) {
        __threadfence();  // make all g_part writes visible
        __shared__ float s_per[BATCH];
        const volatile float2* vp = (const volatile float2*)g_part;
        // 8 warps, each handles 2 batches; lane-strided over that batch's chunks
        #pragma unroll
        for (int t = 0; t < 2; t++) {
            const int bb  = warp * 2 + t;
            const int lo  = s_coff[bb];
            const int hi  = s_coff[bb + 1];
            float fws = 0.0f, fwm = 0.0f;
            for (int k = lo + lane; k < hi; k += 32) {
                fws += vp[k].x;
                fwm += vp[k].y;
            }
            #pragma unroll
            for (int o = 16; o > 0; o >>= 1) {
                fws += __shfl_down_sync(0xFFFFFFFFu, fws, o);
                fwm += __shfl_down_sync(0xFFFFFFFFu, fwm, o);
            }
            if (lane == 0) s_per[bb] = fwm / fws;
        }
        __syncthreads();
        if (tid == 0) {
            float s = 0.0f;
            #pragma unroll
            for (int i = 0; i < BATCH; i++) s += s_per[i];
            out[0] = s * (1.0f / BATCH);
            g_count = 0;   // self-reset for next graph replay
        }
    }
}

extern "C" void kernel_launch(void* const* d_in, const int* in_sizes, int n_in,
                              void* d_out, int out_size)
{
    const float* v_input        = (const float*)d_in[0];
    const float* comparisons    = (const float*)d_in[1];
    const int*   numComparisons = (const int*)  d_in[2];
    float* out = (float*)d_out;

    whdr_kernel<<<MAXCHUNKS, NTHR>>>(v_input, comparisons, numComparisons, out);
}

// round 7
// speedup vs baseline: 1.0165x; 1.0165x over previous
#include <cuda_runtime.h>
#include <cuda_bf16.h>
#include <cuda/atomic>

// Problem constants (fixed by the reference setup_inputs)
#define BATCH        16
#define HW           512
#define MCOMP        200000
#define NTHR         256
#define PAIRS_PER_T  4
#define CHUNK_PAIRS  (PAIRS_PER_T * NTHR)       // 1024 pairs (2048 records) per block
#define MAXPAIRS     (MCOMP / 2)                // 100000
#define MAXCHUNKB    ((MAXPAIRS + CHUNK_PAIRS - 1) / CHUNK_PAIRS)   // 98
#define MAXCHUNKS    (BATCH * MAXCHUNKB)        // 1568

#define EPS_F   1e-10f
#define THR_F   1.1f            // 1.0 + DELTA

// Scratch: per-chunk partial sums (sum_w, sum_w*mismatch) + completion counter
__device__ float2 g_part[MAXCHUNKS];
__device__ unsigned int g_count;   // zero-init; reset by last block each run

__device__ __forceinline__ void whdr_eval(float x1f, float y1f, float x2f, float y2f,
                                          float darkerf, float w,
                                          const float* __restrict__ img,
                                          float& ws, float& wm)
{
    const int x1 = (int)x1f, y1 = (int)y1f;
    const int x2 = (int)x2f, y2 = (int)y2f;
    const int darker = (int)darkerf;

    const float r1 = __ldg(img + y1 * HW + x1);
    const float r2 = __ldg(img + y2 * HW + x2);

    // alg = 1 if r2/(r1+eps) > thr ; 2 if r1/(r2+eps) > thr ; else 0
    int alg = 0;
    if (r2 > THR_F * (r1 + EPS_F))      alg = 1;
    else if (r1 > THR_F * (r2 + EPS_F)) alg = 2;

    ws += w;
    if (alg != darker) wm += w;
}

__global__ __launch_bounds__(NTHR)
void whdr_kernel(const float* __restrict__ v_input,
                 const float* __restrict__ comparisons,
                 const int*   __restrict__ numComparisons,
                 float* __restrict__ out)
{
    __shared__ int s_n[BATCH];
    __shared__ int s_coff[BATCH + 1];   // chunk-offset prefix per batch

    const int tid  = threadIdx.x;
    const int lane = tid & 31;
    const int warp = tid >> 5;

    if (tid < BATCH) s_n[tid] = numComparisons[tid];
    __syncthreads();
    if (tid == 0) {
        int acc = 0;
        s_coff[0] = 0;
        #pragma unroll
        for (int i = 0; i < BATCH; i++) {
            const int pr = s_n[i] >> 1;
            acc += (pr + CHUNK_PAIRS - 1) / CHUNK_PAIRS;
            s_coff[i + 1] = acc;
        }
    }
    __syncthreads();

    const int c = blockIdx.x;
    const int total_chunks = s_coff[BATCH];

    float ws = 0.0f, wm = 0.0f;

    if (c < total_chunks) {
        // find batch of this chunk
        int b = 0;
        #pragma unroll
        for (int i = 1; i < BATCH; i++) b += (c >= s_coff[i]);

        const int nb = s_n[b];
        const int Pb = nb >> 1;
        const int sp = (c - s_coff[b]) * CHUNK_PAIRS;

        const float* __restrict__ img = v_input + (size_t)b * HW * HW;
        const float* __restrict__ cb  = comparisons + (size_t)b * MCOMP * 6;
        const float4* __restrict__ c4 = (const float4*)cb;

        float4 r0[PAIRS_PER_T], r1[PAIRS_PER_T], r2[PAIRS_PER_T];
        float  wmask[PAIRS_PER_T];

        // Issue all 12 streaming 16B loads branchlessly (deep MLP).
        // __ldcs (evict-first) keeps the 58MB comparison stream from evicting
        // the L1-resident image tile that the gathers depend on.
        #pragma unroll
        for (int i = 0; i < PAIRS_PER_T; i++) {
            const int p  = sp + tid + i * NTHR;
            const bool v = p < Pb;
            const size_t pc = v ? (size_t)p : 0;
            r0[i] = __ldcs(c4 + pc * 3 + 0);
            r1[i] = __ldcs(c4 + pc * 3 + 1);
            r2[i] = __ldcs(c4 + pc * 3 + 2);
            wmask[i] = v ? 1.0f : 0.0f;
        }

        #pragma unroll
        for (int i = 0; i < PAIRS_PER_T; i++) {
            // record A: x1,y1,x2,y2 = r0; darker,weight = r1.x,r1.y
            whdr_eval(r0[i].x, r0[i].y, r0[i].z, r0[i].w,
                      r1[i].x, r1[i].y * wmask[i], img, ws, wm);
            // record B: x1,y1 = r1.z,r1.w; x2,y2,darker,weight = r2
            whdr_eval(r1[i].z, r1[i].w, r2[i].x, r2[i].y,
                      r2[i].z, r2[i].w * wmask[i], img, ws, wm);
        }

        // odd leftover record for this batch, once (first chunk, thread 0)
        if ((nb & 1) && tid == 0 && c == s_coff[b]) {
            const int m = nb - 1;
            const float2* c2 = (const float2*)cb;
            const float2 e0 = __ldg(c2 + (size_t)m * 3 + 0);
            const float2 e1 = __ldg(c2 + (size_t)m * 3 + 1);
            const float2 e2 = __ldg(c2 + (size_t)m * 3 + 2);
            whdr_eval(e0.x, e0.y, e1.x, e1.y, e2.x, e2.y, img, ws, wm);
        }
    }

    // block reduction (8 warps)
    __shared__ float s_ws[NTHR / 32];
    __shared__ float s_wm[NTHR / 32];
    #pragma unroll
    for (int o = 16; o > 0; o >>= 1) {
        ws += __shfl_down_sync(0xFFFFFFFFu, ws, o);
        wm += __shfl_down_sync(0xFFFFFFFFu, wm, o);
    }
    if (lane == 0) { s_ws[warp] = ws; s_wm[warp] = wm; }
    __syncthreads();

    __shared__ bool s_last;
    if (warp == 0) {
        ws = (lane < NTHR / 32) ? s_ws[lane] : 0.0f;
        wm = (lane < NTHR / 32) ? s_wm[lane] : 0.0f;
        #pragma unroll
        for (int o = 4; o > 0; o >>= 1) {
            ws += __shfl_down_sync(0xFFFFFFFFu, ws, o);
            wm += __shfl_down_sync(0xFFFFFFFFu, wm, o);
        }
        if (lane == 0) {
            // plain store, published by the release below
            g_part[c] = make_float2(ws, wm);
            // acq_rel fetch_add at device scope: release publishes g_part[c],
            // acquire pairs with every other block's release. Compiles to a
            // strong GPU-scope L2 atomic — no CCTL.IVALL, so co-resident
            // blocks keep their L1 image cache (unlike __threadfence).
            cuda::atomic_ref<unsigned int, cuda::thread_scope_device> cnt(g_count);
            unsigned int prev = cnt.fetch_add(1u, cuda::memory_order_acq_rel);
            s_last = (prev == (unsigned int)(gridDim.x - 1));
        }
    }
    __syncthreads();

    // Last block performs the deterministic final reduction.
    // Reads use __ldcg (L2-coherent, bypasses L1) — paired with the acq_rel
    // atomic above this sees all published partials.
    if (s_last) {
        __shared__ float s_per[BATCH];
        // 8 warps, each handles 2 batches; lane-strided over that batch's chunks
        #pragma unroll
        for (int t = 0; t < 2; t++) {
            const int bb  = warp * 2 + t;
            const int lo  = s_coff[bb];
            const int hi  = s_coff[bb + 1];
            float fws = 0.0f, fwm = 0.0f;
            for (int k = lo + lane; k < hi; k += 32) {
                const float2 p = __ldcg(&g_part[k]);
                fws += p.x;
                fwm += p.y;
            }
            #pragma unroll
            for (int o = 16; o > 0; o >>= 1) {
                fws += __shfl_down_sync(0xFFFFFFFFu, fws, o);
                fwm += __shfl_down_sync(0xFFFFFFFFu, fwm, o);
            }
            if (lane == 0) s_per[bb] = fwm / fws;
        }
        __syncthreads();
        if (tid == 0) {
            float s = 0.0f;
            #pragma unroll
            for (int i = 0; i < BATCH; i++) s += s_per[i];
            out[0] = s * (1.0f / BATCH);
            g_count = 0;   // self-reset for next graph replay
        }
    }
}

extern "C" void kernel_launch(void* const* d_in, const int* in_sizes, int n_in,
                              void* d_out, int out_size)
{
    const float* v_input        = (const float*)d_in[0];
    const float* comparisons    = (const float*)d_in[1];
    const int*   numComparisons = (const int*)  d_in[2];
    float* out = (float*)d_out;

    whdr_kernel<<<MAXCHUNKS, NTHR>>>(v_input, comparisons, numComparisons, out);
}

// round 8
// speedup vs baseline: 1.1521x; 1.1333x over previous
#include <cuda_runtime.h>
#include <cuda_bf16.h>
#include <cuda/atomic>

// Problem constants (fixed by the reference setup_inputs)
#define BATCH   16
#define HW      512
#define MCOMP   200000
#define NBLK    64
#define NTHR    256
#define TOTAL_BLOCKS (BATCH * NBLK)

#define EPS_F   1e-10f
#define THR_F   1.1f            // 1.0 + DELTA

// Scratch: per-block partial sums (sum_w, sum_w*mismatch) + completion counter
__device__ float2 g_part[TOTAL_BLOCKS];
__device__ unsigned int g_count;   // zero-init; reset by last block each run

__device__ __forceinline__ void whdr_one(const float* __restrict__ img,
                                         const float2* __restrict__ c2,
                                         int m, float& ws, float& wm)
{
    const float2 p0 = c2[m * 3 + 0];   // (x1, y1)
    const float2 p1 = c2[m * 3 + 1];   // (x2, y2)
    const float2 p2 = c2[m * 3 + 2];   // (darker, weight)

    const int x1 = (int)p0.x, y1 = (int)p0.y;
    const int x2 = (int)p1.x, y2 = (int)p1.y;
    const int darker = (int)p2.x;
    const float w = p2.y;

    const float r1 = __ldg(img + y1 * HW + x1);
    const float r2 = __ldg(img + y2 * HW + x2);

    // alg = 1 if r2/(r1+eps) > thr ; 2 if r1/(r2+eps) > thr ; else 0
    // multiply-form (all values positive) avoids divides
    int alg = 0;
    if (r2 > THR_F * (r1 + EPS_F))      alg = 1;
    else if (r1 > THR_F * (r2 + EPS_F)) alg = 2;

    ws += w;
    if (alg != darker) wm += w;
}

__global__ __launch_bounds__(NTHR)
void whdr_kernel(const float* __restrict__ v_input,
                 const float* __restrict__ comparisons,
                 const int*   __restrict__ numComparisons,
                 float* __restrict__ out)
{
    const int b   = blockIdx.y;
    const int blk = blockIdx.x;
    const float* __restrict__ img = v_input + (size_t)b * HW * HW;
    const float2* __restrict__ c2 =
        (const float2*)(comparisons + (size_t)b * MCOMP * 6);
    const int n = numComparisons[b];

    float ws0 = 0.0f, wm0 = 0.0f;
    float ws1 = 0.0f, wm1 = 0.0f;

    // Persistent grid-stride loop with plain (evict-normal) loads.
    // Evict-normal keeps the 77MB comparison stream + 17MB images L2-resident
    // across graph replays (93.6MB < 126MB L2) — __ldcs forced a full DRAM
    // re-stream every replay (the R3-R7 regression).
    const int stride = NBLK * NTHR;
    int m = blk * NTHR + threadIdx.x;
    for (; m + stride < n; m += 2 * stride) {
        whdr_one(img, c2, m,          ws0, wm0);
        whdr_one(img, c2, m + stride, ws1, wm1);
    }
    if (m < n) whdr_one(img, c2, m, ws0, wm0);

    float ws = ws0 + ws1;
    float wm = wm0 + wm1;

    // block reduction (8 warps)
    __shared__ float s_ws[NTHR / 32];
    __shared__ float s_wm[NTHR / 32];
    const int lane = threadIdx.x & 31;
    const int warp = threadIdx.x >> 5;
    #pragma unroll
    for (int o = 16; o > 0; o >>= 1) {
        ws += __shfl_down_sync(0xFFFFFFFFu, ws, o);
        wm += __shfl_down_sync(0xFFFFFFFFu, wm, o);
    }
    if (lane == 0) { s_ws[warp] = ws; s_wm[warp] = wm; }
    __syncthreads();

    __shared__ bool s_last;
    if (warp == 0) {
        ws = (lane < NTHR / 32) ? s_ws[lane] : 0.0f;
        wm = (lane < NTHR / 32) ? s_wm[lane] : 0.0f;
        #pragma unroll
        for (int o = 4; o > 0; o >>= 1) {
            ws += __shfl_down_sync(0xFFFFFFFFu, ws, o);
            wm += __shfl_down_sync(0xFFFFFFFFu, wm, o);
        }
        if (lane == 0) {
            // plain store, published by the release below
            g_part[b * NBLK + blk] = make_float2(ws, wm);
            // acq_rel fetch_add at device scope: release publishes our g_part
            // store; acquire pairs with every other block's release. L2 atomic,
            // no CCTL.IVALL L1 flush.
            cuda::atomic_ref<unsigned int, cuda::thread_scope_device> cnt(g_count);
            unsigned int prev = cnt.fetch_add(1u, cuda::memory_order_acq_rel);
            s_last = (prev == TOTAL_BLOCKS - 1);
        }
    }
    __syncthreads();

    // Last block performs the deterministic final reduction.
    // __ldcg reads (L2-coherent, bypass L1) see all published partials.
    if (s_last) {
        __shared__ float s_per[BATCH];
        // 8 warps, each handles 2 batches (64 partials per batch)
        #pragma unroll
        for (int t = 0; t < 2; t++) {
            const int bb = warp * 2 + t;
            const float2 pa = __ldcg(&g_part[bb * NBLK + lane]);
            const float2 pb = __ldcg(&g_part[bb * NBLK + 32 + lane]);
            float fws = pa.x + pb.x;
            float fwm = pa.y + pb.y;
            #pragma unroll
            for (int o = 16; o > 0; o >>= 1) {
                fws += __shfl_down_sync(0xFFFFFFFFu, fws, o);
                fwm += __shfl_down_sync(0xFFFFFFFFu, fwm, o);
            }
            if (lane == 0) s_per[bb] = fwm / fws;
        }
        __syncthreads();
        if (threadIdx.x == 0) {
            float s = 0.0f;
            #pragma unroll
            for (int i = 0; i < BATCH; i++) s += s_per[i];
            out[0] = s * (1.0f / BATCH);
            g_count = 0;   // self-reset for next graph replay
        }
    }
}

extern "C" void kernel_launch(void* const* d_in, const int* in_sizes, int n_in,
                              void* d_out, int out_size)
{
    const float* v_input        = (const float*)d_in[0];
    const float* comparisons    = (const float*)d_in[1];
    const int*   numComparisons = (const int*)  d_in[2];
    float* out = (float*)d_out;

    dim3 grid(NBLK, BATCH, 1);
    whdr_kernel<<<grid, NTHR>>>(v_input, comparisons, numComparisons, out);
}